// round 10
// baseline (speedup 1.0000x reference)
#include <cuda_runtime.h>
#include <cstddef>

// ProdLayer forward: element_mars[nids] = node_mars[cids].sum(axis=1)
//   d_in[0] node_mars     float32  [N_SRC, 128]
//   d_in[1] element_mars  float32  [N_PROD+1, 128]
//   d_in[2] nids          int32    [N_PROD]
//   d_in[3] cids          int32    [N_PROD, 4]
// Output: float32 [N_PROD+1, 128]
//
// R10: R2's converged flat structure (warp-per-product, float4 lanes,
// 256-thread CTAs, __ldcs index reads, __stcs streaming stores) with one
// change: gathers use __ldcg (ld.global.cg = L2-only, L1 bypass). L1 hit
// rate on a uniform-random 512 MB gather is ~0 (no cross-SM sharing,
// 228 KB/SM vs 3.5 MB/SM working-set share), so L1 allocation is pure
// tag/wavefront-queue overhead (nL=4 lines per LDG.128 warp access).
// Bypassing shortens the L1TEX path; DRAM bytes identical.
//
// Locked-in findings from R1-R9:
//  - flat launch beats persistent grid-stride (CTA replacement pipelines
//    load issue for free; loops serialize it): R7/R8 regressed.
//  - L2 hit rate pinned at 126MB/512MB capacity ratio; policies (R5) and
//    column tiling (R3, sector-tag amplification) both falsified.
//  - MLP 4 vs 8 per warp and CTA size 128 vs 256: neutral (R6, R9).

static constexpr int B_F4 = 32;  // 128 floats / 4 per row

__global__ void __launch_bounds__(256) prodlayer_kernel(
    const float4* __restrict__ node_mars,
    const float4* __restrict__ element_mars,
    const int*    __restrict__ nids,
    const int4*   __restrict__ cids,
    float4*       __restrict__ out,
    int n_prod)
{
    const int gwarp = (int)((blockIdx.x * (unsigned)blockDim.x + threadIdx.x) >> 5);
    const int lane  = threadIdx.x & 31;

    if (gwarp < n_prod) {
        const int4 c = __ldcs(&cids[gwarp]);

        const float4 a = __ldcg(&node_mars[(size_t)c.x * B_F4 + lane]);
        const float4 b = __ldcg(&node_mars[(size_t)c.y * B_F4 + lane]);
        const float4 d = __ldcg(&node_mars[(size_t)c.z * B_F4 + lane]);
        const float4 e = __ldcg(&node_mars[(size_t)c.w * B_F4 + lane]);

        float4 s;
        s.x = (a.x + b.x) + (d.x + e.x);
        s.y = (a.y + b.y) + (d.y + e.y);
        s.z = (a.z + b.z) + (d.z + e.z);
        s.w = (a.w + b.w) + (d.w + e.w);

        const int o = __ldcs(&nids[gwarp]);
        __stcs(&out[(size_t)o * B_F4 + lane], s);
    } else if (gwarp == n_prod) {
        // Reserved row 0: out row 0 = element_mars row 0 (d_out poisoned).
        __stcs(&out[lane], __ldg(&element_mars[lane]));
    }
}

extern "C" void kernel_launch(void* const* d_in, const int* in_sizes, int n_in,
                              void* d_out, int out_size)
{
    const float4* node_mars    = (const float4*)d_in[0];
    const float4* element_mars = (const float4*)d_in[1];
    const int*    nids         = (const int*)d_in[2];
    const int4*   cids         = (const int4*)d_in[3];
    float4*       out          = (float4*)d_out;

    const int n_prod  = in_sizes[2];          // 500000
    const int n_warps = n_prod + 1;           // +1 warp for reserved row 0
    const int threads = 256;                  // 8 warps per block
    const int blocks  = (n_warps * 32 + threads - 1) / threads;

    prodlayer_kernel<<<blocks, threads>>>(node_mars, element_mars, nids, cids,
                                          out, n_prod);
}